// round 8
// baseline (speedup 1.0000x reference)
#include <cuda_runtime.h>

#define TT 512
#define BB 4096

typedef unsigned long long u64;

// Scratch (allocation APIs forbidden; __device__ globals are the sanctioned path).
// y0 pair-interleaved: [T][B/2][32] u64, each u64 = {val(b_even), val(b_odd)}.
// i index = dir*16 + j. 268 MB.
__device__ u64 g_y0p[(size_t)TT * (BB / 2) * 32];
// gi = bih_l1f + Wih_l1f @ y0 : [T][B][16] float4 (r,z,n,pad). 536 MB.
__device__ float4 g_gi[(size_t)TT * BB * 16];

// ---- packed f32x2 helpers ----
__device__ __forceinline__ u64 pack2(float lo, float hi) {
    u64 r; asm("mov.b64 %0, {%1, %2};" : "=l"(r) : "f"(lo), "f"(hi)); return r;
}
__device__ __forceinline__ void unpack2(u64 v, float& lo, float& hi) {
    asm("mov.b64 {%0, %1}, %2;" : "=f"(lo), "=f"(hi) : "l"(v));
}
__device__ __forceinline__ u64 fma2(u64 a, u64 b, u64 c) {
    u64 d; asm("fma.rn.f32x2 %0, %1, %2, %3;" : "=l"(d) : "l"(a), "l"(b), "l"(c)); return d;
}
__device__ __forceinline__ u64 add2(u64 a, u64 b) {
    u64 d; asm("add.rn.f32x2 %0, %1, %2;" : "=l"(d) : "l"(a), "l"(b)); return d;
}

// ---- fast activations ----
__device__ __forceinline__ float tanh_fast(float x) {
    float y; asm("tanh.approx.f32 %0, %1;" : "=f"(y) : "f"(x)); return y;
}
__device__ __forceinline__ float sigmoid_fast(float x) {
    return fmaf(tanh_fast(0.5f * x), 0.5f, 0.5f);
}

// Padded group stride: 20 u64 = 160B -> the two groups of a warp hit disjoint
// bank sets on each LDS.128 (offset 8 banks), broadcast within a group.
#define HPAD 20

// ---------------------------------------------------------------------------
// Kernel 1: layer 0, both directions (blockIdx.y). 2 elems per lane (f32x2),
// 16 lanes per pair, 8 pairs per 128-thread block -> 2048 warps.
// h exchange via SMEM broadcast (STS.64 + 8 LDS.128), double-buffered,
// ONE __syncwarp per step. No shuffles in the hot loop.
// ---------------------------------------------------------------------------
__global__ void __launch_bounds__(128) gru_l0(
    const float* __restrict__ x,
    const float* __restrict__ WihF, const float* __restrict__ WhhF,
    const float* __restrict__ bihF, const float* __restrict__ bhhF,
    const float* __restrict__ WihB, const float* __restrict__ WhhB,
    const float* __restrict__ bihB, const float* __restrict__ bhhB)
{
    __shared__ __align__(16) u64 hbuf[2][8][HPAD];

    const int tid = threadIdx.x;
    const int j = tid & 15;
    const int g = tid >> 4;                      // group 0..7
    const int P = blockIdx.x * 8 + g;            // pair index
    const int b0 = 2 * P;
    const bool bwd = (blockIdx.y != 0);

    const float* Wih = bwd ? WihB : WihF;
    const float* Whh = bwd ? WhhB : WhhF;
    const float* bih = bwd ? bihB : bihF;
    const float* bhh = bwd ? bhhB : bhhF;

    u64 wr2[16], wz2[16], wn2[16];
#pragma unroll
    for (int k = 0; k < 16; ++k) {
        float a = Whh[(j)      * 16 + k];
        float b = Whh[(j + 16) * 16 + k];
        float c = Whh[(j + 32) * 16 + k];
        wr2[k] = pack2(a, a);
        wz2[k] = pack2(b, b);
        wn2[k] = pack2(c, c);
    }
    const u64 wir2 = pack2(Wih[j], Wih[j]);
    const u64 wiz2 = pack2(Wih[j + 16], Wih[j + 16]);
    const u64 win2 = pack2(Wih[j + 32], Wih[j + 32]);
    const u64 bir2 = pack2(bih[j], bih[j]);
    const u64 biz2 = pack2(bih[j + 16], bih[j + 16]);
    const u64 bin2 = pack2(bih[j + 32], bih[j + 32]);
    const u64 bhr2 = pack2(bhh[j], bhh[j]);
    const u64 bhz2 = pack2(bhh[j + 16], bhh[j + 16]);
    const u64 bhn2 = pack2(bhh[j + 32], bhh[j + 32]);

    const int dt = bwd ? -1 : 1;
    const int t0 = bwd ? TT - 1 : 0;
    const int dir16 = bwd ? 16 : 0;

    const float* xq0 = x + (size_t)b0 * TT + t0;       // x is [B, T, 1]
    const float* xq1 = xq0 + TT;

    const long ystep = (long)((BB / 2) * 32) * dt;     // u64 units per t
    u64* yq = g_y0p + (size_t)t0 * ((BB / 2) * 32) + (size_t)P * 32 + dir16 + j;

    // init h buffers (slot 0 is read at s=0)
    hbuf[0][g][j] = 0ull;
    __syncwarp();

    u64 h2 = 0ull;
    u64 xv2 = pack2(*xq0, *xq1);
    for (int s = 0; s < TT; ++s) {
        u64 xnext = 0ull;
        if (s + 1 < TT) {
            const int off = dt * (s + 1);
            xnext = pack2(xq0[off], xq1[off]);
        }

        const ulonglong2* hp = (const ulonglong2*)&hbuf[s & 1][g][0];
        u64 ar = bhr2, az = bhz2, an = bhn2;
#pragma unroll
        for (int q = 0; q < 8; ++q) {
            ulonglong2 hh = hp[q];                      // LDS.128 broadcast
            ar = fma2(wr2[2 * q],     hh.x, ar);
            az = fma2(wz2[2 * q],     hh.x, az);
            an = fma2(wn2[2 * q],     hh.x, an);
            ar = fma2(wr2[2 * q + 1], hh.y, ar);
            az = fma2(wz2[2 * q + 1], hh.y, az);
            an = fma2(wn2[2 * q + 1], hh.y, an);
        }

        u64 pr = add2(fma2(xv2, wir2, bir2), ar);
        u64 pz = add2(fma2(xv2, wiz2, biz2), az);
        float prx, pry, pzx, pzy;
        unpack2(pr, prx, pry);
        unpack2(pz, pzx, pzy);
        float r0 = sigmoid_fast(prx), r1 = sigmoid_fast(pry);
        float z0 = sigmoid_fast(pzx), z1 = sigmoid_fast(pzy);

        u64 pn = fma2(pack2(r0, r1), an, fma2(xv2, win2, bin2));
        float pnx, pny;
        unpack2(pn, pnx, pny);
        float n0 = tanh_fast(pnx), n1 = tanh_fast(pny);

        float h0, h1;
        unpack2(h2, h0, h1);
        h0 = n0 + z0 * (h0 - n0);
        h1 = n1 + z1 * (h1 - n1);
        h2 = pack2(h0, h1);

        hbuf[(s & 1) ^ 1][g][j] = h2;                   // STS.64 for next step
        __syncwarp();

        *yq = h2;                                       // STG.64 pair
        yq += ystep;
        xv2 = xnext;
    }
}

// ---------------------------------------------------------------------------
// Kernel 2: layer-1 forward input projection, TIME-PARALLEL, f32x2
// (unchanged from R7; few shuffles, model-fast).
// ---------------------------------------------------------------------------
__global__ void __launch_bounds__(128) l1_proj(
    const float* __restrict__ Wih, const float* __restrict__ bih)
{
    const int lane = threadIdx.x & 31;
    const int wrp = threadIdx.x >> 5;
    const int half = lane >> 4;
    const int j = lane & 15;
    const int p = blockIdx.x * 4 + wrp;      // pair index
    const int b0 = 2 * p;
    const int t0 = blockIdx.y * 32;

    const float* Wr = Wih + (j)      * 32 + half * 16;
    const float* Wz = Wih + (j + 16) * 32 + half * 16;
    const float* Wn = Wih + (j + 32) * 32 + half * 16;
    u64 w0[16], w1[16], w2[16];
#pragma unroll
    for (int k = 0; k < 16; ++k) {
        w0[k] = pack2(Wr[k], Wr[k]);
        w1[k] = pack2(Wz[k], Wz[k]);
        w2[k] = pack2(Wn[k], Wn[k]);
    }
    const u64 bg0 = half ? 0ull : pack2(bih[j],      bih[j]);
    const u64 bg1 = half ? 0ull : pack2(bih[j + 16], bih[j + 16]);
    const u64 bg2 = half ? 0ull : pack2(bih[j + 32], bih[j + 32]);

    const ulonglong2* yrow =
        (const ulonglong2*)(g_y0p + ((size_t)t0 * (BB / 2) + p) * 32) + half * 8;
    float4* go = g_gi + ((size_t)t0 * BB + (b0 + half)) * 16 + j;

#pragma unroll 2
    for (int t = 0; t < 32; ++t) {
        u64 v[16];
#pragma unroll
        for (int q = 0; q < 8; ++q) {
            ulonglong2 u = yrow[q];
            v[2 * q] = u.x;
            v[2 * q + 1] = u.y;
        }
        u64 a0 = bg0, a1 = bg1, a2 = bg2;
#pragma unroll
        for (int k = 0; k < 16; ++k) {
            a0 = fma2(w0[k], v[k], a0);
            a1 = fma2(w1[k], v[k], a1);
            a2 = fma2(w2[k], v[k], a2);
        }
        a0 = add2(a0, __shfl_xor_sync(0xFFFFFFFFu, a0, 16));
        a1 = add2(a1, __shfl_xor_sync(0xFFFFFFFFu, a1, 16));
        a2 = add2(a2, __shfl_xor_sync(0xFFFFFFFFu, a2, 16));

        float l0v, h0v, l1v, h1v, l2v, h2v;
        unpack2(a0, l0v, h0v);
        unpack2(a1, l1v, h1v);
        unpack2(a2, l2v, h2v);
        float4 o;
        o.x = half ? h0v : l0v;
        o.y = half ? h1v : l1v;
        o.z = half ? h2v : l2v;
        o.w = 0.0f;
        *go = o;

        yrow += (size_t)(BB / 2) * 16;
        go += (size_t)BB * 16;
    }
}

// ---------------------------------------------------------------------------
// Kernel 3: layer-1 forward recurrence. SMEM h exchange (no shuffles),
// depth-4 ring prefetch of packed gi, f32x2 math.
// ---------------------------------------------------------------------------
__global__ void __launch_bounds__(128) gru_l1f(
    const float* __restrict__ Whh, const float* __restrict__ bhh,
    float* __restrict__ out)
{
    __shared__ __align__(16) u64 hbuf[2][8][HPAD];

    const int tid = threadIdx.x;
    const int j = tid & 15;
    const int g = tid >> 4;
    const int P = blockIdx.x * 8 + g;
    const int b0 = 2 * P;

    u64 wr2[16], wz2[16], wn2[16];
#pragma unroll
    for (int k = 0; k < 16; ++k) {
        float a = Whh[(j)      * 16 + k];
        float b = Whh[(j + 16) * 16 + k];
        float c = Whh[(j + 32) * 16 + k];
        wr2[k] = pack2(a, a);
        wz2[k] = pack2(b, b);
        wn2[k] = pack2(c, c);
    }
    const u64 bhr2 = pack2(bhh[j], bhh[j]);
    const u64 bhz2 = pack2(bhh[j + 16], bhh[j + 16]);
    const u64 bhn2 = pack2(bhh[j + 32], bhh[j + 32]);

    const size_t ts = (size_t)BB * 16;                 // float4 stride per t
    const float4* gp0 = g_gi + (size_t)b0 * 16 + j;
    const float4* gp1 = gp0 + 16;
    const float4* pf0 = gp0 + 4 * ts;
    const float4* pf1 = pf0 + 16;

    u64 rr[4], rz[4], rn[4];
#pragma unroll
    for (int q = 0; q < 4; ++q) {
        float4 A = gp0[(size_t)q * ts];
        float4 B = gp1[(size_t)q * ts];
        rr[q] = pack2(A.x, B.x);
        rz[q] = pack2(A.y, B.y);
        rn[q] = pack2(A.z, B.z);
    }

    hbuf[0][g][j] = 0ull;
    __syncwarp();

    u64 h2 = 0ull;
    for (int t = 0; t < TT; ++t) {
        const int sl = t & 3;
        u64 gr2 = rr[sl], gz2 = rz[sl], gn2 = rn[sl];
        if (t + 4 < TT) {
            float4 A = *pf0;
            float4 B = *pf1;
            rr[sl] = pack2(A.x, B.x);
            rz[sl] = pack2(A.y, B.y);
            rn[sl] = pack2(A.z, B.z);
        }
        pf0 += ts; pf1 += ts;

        const ulonglong2* hp = (const ulonglong2*)&hbuf[t & 1][g][0];
        u64 ar = bhr2, az = bhz2, an = bhn2;
#pragma unroll
        for (int q = 0; q < 8; ++q) {
            ulonglong2 hh = hp[q];
            ar = fma2(wr2[2 * q],     hh.x, ar);
            az = fma2(wz2[2 * q],     hh.x, az);
            an = fma2(wn2[2 * q],     hh.x, an);
            ar = fma2(wr2[2 * q + 1], hh.y, ar);
            az = fma2(wz2[2 * q + 1], hh.y, az);
            an = fma2(wn2[2 * q + 1], hh.y, an);
        }

        u64 pr = add2(gr2, ar);
        u64 pz = add2(gz2, az);

        float prx, pry, pzx, pzy;
        unpack2(pr, prx, pry);
        unpack2(pz, pzx, pzy);
        float r0 = sigmoid_fast(prx), r1 = sigmoid_fast(pry);
        float z0 = sigmoid_fast(pzx), z1 = sigmoid_fast(pzy);

        u64 pn = fma2(pack2(r0, r1), an, gn2);
        float pnx, pny;
        unpack2(pn, pnx, pny);
        float n0 = tanh_fast(pnx), n1 = tanh_fast(pny);

        float h0, h1;
        unpack2(h2, h0, h1);
        h0 = n0 + z0 * (h0 - n0);
        h1 = n1 + z1 * (h1 - n1);
        h2 = pack2(h0, h1);

        hbuf[(t & 1) ^ 1][g][j] = h2;
        __syncwarp();
    }

    float h0, h1;
    unpack2(h2, h0, h1);
    out[b0 * 32 + j] = h0;
    out[(b0 + 1) * 32 + j] = h1;
}

// ---------------------------------------------------------------------------
// Kernel 4: layer-1 backward at position T-1 == one GRU step from h=0 on
// y0[T-1] (lax.scan reverse alignment). 17us measured — unchanged.
// ---------------------------------------------------------------------------
__global__ void __launch_bounds__(128) gru_l1b(
    const float* __restrict__ Wih,
    const float* __restrict__ bih, const float* __restrict__ bhh,
    float* __restrict__ out)
{
    const int tid = threadIdx.x;
    const int j = tid & 15;
    const int e = tid >> 4;
    const int b = blockIdx.x * 8 + e;
    const int p = b >> 1;
    const int sel = b & 1;

    float wi0[32], wi1[32], wi2[32];
#pragma unroll
    for (int k = 0; k < 32; ++k) {
        wi0[k] = Wih[(j)      * 32 + k];
        wi1[k] = Wih[(j + 16) * 32 + k];
        wi2[k] = Wih[(j + 32) * 32 + k];
    }
    const float bir = bih[j], biz = bih[j + 16], bin_ = bih[j + 32];
    const float bhr = bhh[j], bhz = bhh[j + 16], bhn = bhh[j + 32];

    const ulonglong2* yrow =
        (const ulonglong2*)(g_y0p + ((size_t)(TT - 1) * (BB / 2) + p) * 32);
    ulonglong2 u2 = yrow[j];
    float ax, bx, ay, by;
    unpack2(u2.x, ax, bx);
    unpack2(u2.y, ay, by);
    float2 my;
    my.x = sel ? bx : ax;
    my.y = sel ? by : ay;

    float ir = bir, iz = biz, in_ = bin_;
#pragma unroll
    for (int k = 0; k < 16; ++k) {
        float vx = __shfl_sync(0xFFFFFFFFu, my.x, k, 16);
        float vy = __shfl_sync(0xFFFFFFFFu, my.y, k, 16);
        ir  = fmaf(wi0[2 * k], vx, ir);  ir  = fmaf(wi0[2 * k + 1], vy, ir);
        iz  = fmaf(wi1[2 * k], vx, iz);  iz  = fmaf(wi1[2 * k + 1], vy, iz);
        in_ = fmaf(wi2[2 * k], vx, in_); in_ = fmaf(wi2[2 * k + 1], vy, in_);
    }
    float r = sigmoid_fast(ir + bhr);
    float z = sigmoid_fast(iz + bhz);
    float n = tanh_fast(fmaf(r, bhn, in_));
    out[b * 32 + 16 + j] = (1.0f - z) * n;   // h0 = 0
}

// ---------------------------------------------------------------------------
// Launch. Inputs: x, then (Wih, Whh, bih, bhh) for l0_f, l0_b, l1_f, l1_b.
// Order: l0, l1b, proj, l1f (last launch = ncu capture slot = l1f).
// ---------------------------------------------------------------------------
extern "C" void kernel_launch(void* const* d_in, const int* in_sizes, int n_in,
                              void* d_out, int out_size) {
    const float* x = (const float*)d_in[0];

    dim3 g1(BB / 16, 2);
    gru_l0<<<g1, 128>>>(x,
        (const float*)d_in[1],  (const float*)d_in[2],
        (const float*)d_in[3],  (const float*)d_in[4],
        (const float*)d_in[5],  (const float*)d_in[6],
        (const float*)d_in[7],  (const float*)d_in[8]);

    gru_l1b<<<BB / 8, 128>>>(
        (const float*)d_in[13],
        (const float*)d_in[15], (const float*)d_in[16],
        (float*)d_out);

    dim3 g2(BB / 8, TT / 32);
    l1_proj<<<g2, 128>>>(
        (const float*)d_in[9],  (const float*)d_in[11]);

    gru_l1f<<<BB / 16, 128>>>(
        (const float*)d_in[10], (const float*)d_in[12],
        (float*)d_out);
}

// round 10
// speedup vs baseline: 1.1235x; 1.1235x over previous
#include <cuda_runtime.h>
#include <cuda_fp16.h>

#define TT 512
#define BB 4096

typedef unsigned long long u64;

// Scratch (allocation APIs forbidden; __device__ globals are the sanctioned path).
// y0 pair-interleaved: [T][B/2][32] u64, each u64 = {val(b_even), val(b_odd)}.
// i index = dir*16 + j. 268 MB.
__device__ u64 g_y0p[(size_t)TT * (BB / 2) * 32];
// gi packed fp16: [T][B/2][16] uint4 = {half2 r, half2 z, half2 n, pad},
// each half2 = {elem b0, elem b0+1}. 268 MB.
__device__ uint4 g_gi[(size_t)TT * (BB / 2) * 16];

// ---- packed f32x2 helpers ----
__device__ __forceinline__ u64 pack2(float lo, float hi) {
    u64 r; asm("mov.b64 %0, {%1, %2};" : "=l"(r) : "f"(lo), "f"(hi)); return r;
}
__device__ __forceinline__ void unpack2(u64 v, float& lo, float& hi) {
    asm("mov.b64 {%0, %1}, %2;" : "=f"(lo), "=f"(hi) : "l"(v));
}
__device__ __forceinline__ u64 fma2(u64 a, u64 b, u64 c) {
    u64 d; asm("fma.rn.f32x2 %0, %1, %2, %3;" : "=l"(d) : "l"(a), "l"(b), "l"(c)); return d;
}
__device__ __forceinline__ u64 add2(u64 a, u64 b) {
    u64 d; asm("add.rn.f32x2 %0, %1, %2;" : "=l"(d) : "l"(a), "l"(b)); return d;
}

// ---- fast activations ----
__device__ __forceinline__ float tanh_fast(float x) {
    float y; asm("tanh.approx.f32 %0, %1;" : "=f"(y) : "f"(x)); return y;
}
__device__ __forceinline__ float sigmoid_fast(float x) {
    return fmaf(tanh_fast(0.5f * x), 0.5f, 0.5f);
}

// half2 (as uint) -> f32x2 pair
__device__ __forceinline__ u64 h2_to_pair(unsigned int h) {
    float2 f = __half22float2(*reinterpret_cast<const __half2*>(&h));
    return pack2(f.x, f.y);
}
__device__ __forceinline__ unsigned int pair_to_h2(u64 v) {
    float lo, hi;
    unpack2(v, lo, hi);
    __half2 h = __floats2half2_rn(lo, hi);
    return *reinterpret_cast<const unsigned int*>(&h);
}

// ---------------------------------------------------------------------------
// Kernel 1: layer 0 (R7 version — best measured). Both directions via
// blockIdx.y; FOUR elements per lane = two independent f32x2 chains sharing
// register weights; shuffle h-exchange (SMEM variant measured 2x slower).
// ---------------------------------------------------------------------------
__global__ void __launch_bounds__(64) gru_l0(
    const float* __restrict__ x,
    const float* __restrict__ WihF, const float* __restrict__ WhhF,
    const float* __restrict__ bihF, const float* __restrict__ bhhF,
    const float* __restrict__ WihB, const float* __restrict__ WhhB,
    const float* __restrict__ bihB, const float* __restrict__ bhhB)
{
    const int tid = threadIdx.x;
    const int j = tid & 15;
    const int g = tid >> 4;                       // group 0..3
    const int b0 = (blockIdx.x * 4 + g) * 4;      // elements b0..b0+3
    const bool bwd = (blockIdx.y != 0);

    const float* Wih = bwd ? WihB : WihF;
    const float* Whh = bwd ? WhhB : WhhF;
    const float* bih = bwd ? bihB : bihF;
    const float* bhh = bwd ? bhhB : bhhF;

    u64 wr2[16], wz2[16], wn2[16];
#pragma unroll
    for (int k = 0; k < 16; ++k) {
        float a = Whh[(j)      * 16 + k];
        float b = Whh[(j + 16) * 16 + k];
        float c = Whh[(j + 32) * 16 + k];
        wr2[k] = pack2(a, a);
        wz2[k] = pack2(b, b);
        wn2[k] = pack2(c, c);
    }
    const u64 wir2 = pack2(Wih[j], Wih[j]);
    const u64 wiz2 = pack2(Wih[j + 16], Wih[j + 16]);
    const u64 win2 = pack2(Wih[j + 32], Wih[j + 32]);
    const u64 bir2 = pack2(bih[j], bih[j]);
    const u64 biz2 = pack2(bih[j + 16], bih[j + 16]);
    const u64 bin2 = pack2(bih[j + 32], bih[j + 32]);
    const u64 bhr2 = pack2(bhh[j], bhh[j]);
    const u64 bhz2 = pack2(bhh[j + 16], bhh[j + 16]);
    const u64 bhn2 = pack2(bhh[j + 32], bhh[j + 32]);

    const int dt = bwd ? -1 : 1;
    const int t0 = bwd ? TT - 1 : 0;
    const int dir16 = bwd ? 16 : 0;

    const float* xA0 = x + (size_t)b0 * TT + t0;       // x is [B, T, 1]
    const float* xA1 = xA0 + TT;
    const float* xB0 = xA0 + 2 * TT;
    const float* xB1 = xA0 + 3 * TT;

    const long ystep = (long)((BB / 2) * 32) * dt;     // u64 units per t
    u64* yq = g_y0p + (size_t)t0 * ((BB / 2) * 32) + (size_t)(b0 >> 1) * 32 + dir16 + j;

    u64 hA = 0ull, hB = 0ull;
    u64 xvA = pack2(*xA0, *xA1);
    u64 xvB = pack2(*xB0, *xB1);

    for (int s = 0; s < TT; ++s) {
        u64 xnA = 0ull, xnB = 0ull;
        if (s + 1 < TT) {
            const int off = dt * (s + 1);
            xnA = pack2(xA0[off], xA1[off]);
            xnB = pack2(xB0[off], xB1[off]);
        }

        u64 arA = bhr2, azA = bhz2, anA = bhn2;
        u64 arB = bhr2, azB = bhz2, anB = bhn2;
#pragma unroll
        for (int k = 0; k < 16; ++k) {
            u64 hkA = __shfl_sync(0xFFFFFFFFu, hA, k, 16);
            u64 hkB = __shfl_sync(0xFFFFFFFFu, hB, k, 16);
            arA = fma2(wr2[k], hkA, arA);
            arB = fma2(wr2[k], hkB, arB);
            azA = fma2(wz2[k], hkA, azA);
            azB = fma2(wz2[k], hkB, azB);
            anA = fma2(wn2[k], hkA, anA);
            anB = fma2(wn2[k], hkB, anB);
        }

        // pair A gates
        u64 prA = add2(fma2(xvA, wir2, bir2), arA);
        u64 pzA = add2(fma2(xvA, wiz2, biz2), azA);
        float prx, pry, pzx, pzy;
        unpack2(prA, prx, pry);
        unpack2(pzA, pzx, pzy);
        float rA0 = sigmoid_fast(prx), rA1 = sigmoid_fast(pry);
        float zA0 = sigmoid_fast(pzx), zA1 = sigmoid_fast(pzy);
        u64 pnA = fma2(pack2(rA0, rA1), anA, fma2(xvA, win2, bin2));
        float pnx, pny;
        unpack2(pnA, pnx, pny);
        float nA0 = tanh_fast(pnx), nA1 = tanh_fast(pny);
        float hA0, hA1;
        unpack2(hA, hA0, hA1);
        hA0 = nA0 + zA0 * (hA0 - nA0);
        hA1 = nA1 + zA1 * (hA1 - nA1);
        hA = pack2(hA0, hA1);

        // pair B gates
        u64 prB = add2(fma2(xvB, wir2, bir2), arB);
        u64 pzB = add2(fma2(xvB, wiz2, biz2), azB);
        unpack2(prB, prx, pry);
        unpack2(pzB, pzx, pzy);
        float rB0 = sigmoid_fast(prx), rB1 = sigmoid_fast(pry);
        float zB0 = sigmoid_fast(pzx), zB1 = sigmoid_fast(pzy);
        u64 pnB = fma2(pack2(rB0, rB1), anB, fma2(xvB, win2, bin2));
        unpack2(pnB, pnx, pny);
        float nB0 = tanh_fast(pnx), nB1 = tanh_fast(pny);
        float hB0, hB1;
        unpack2(hB, hB0, hB1);
        hB0 = nB0 + zB0 * (hB0 - nB0);
        hB1 = nB1 + zB1 * (hB1 - nB1);
        hB = pack2(hB0, hB1);

        yq[0]  = hA;      // pair (b0, b0+1)
        yq[32] = hB;      // pair (b0+2, b0+3)
        yq += ystep;
        xvA = xnA;
        xvB = xnB;
    }
}

// ---------------------------------------------------------------------------
// Kernel 2: layer-1 forward input projection (R7 structure). After the
// shfl_xor(16) reduction BOTH halves hold the full pair result, so only
// half 0 stores: one uint4 {h2 r, h2 z, h2 n, 0} per (pair, j) -> fp16,
// half the write traffic of R7.
// ---------------------------------------------------------------------------
__global__ void __launch_bounds__(128) l1_proj(
    const float* __restrict__ Wih, const float* __restrict__ bih)
{
    const int lane = threadIdx.x & 31;
    const int wrp = threadIdx.x >> 5;
    const int half = lane >> 4;
    const int j = lane & 15;
    const int p = blockIdx.x * 4 + wrp;      // pair index
    const int t0 = blockIdx.y * 32;

    const float* Wr = Wih + (j)      * 32 + half * 16;
    const float* Wz = Wih + (j + 16) * 32 + half * 16;
    const float* Wn = Wih + (j + 32) * 32 + half * 16;
    u64 w0[16], w1[16], w2[16];
#pragma unroll
    for (int k = 0; k < 16; ++k) {
        w0[k] = pack2(Wr[k], Wr[k]);
        w1[k] = pack2(Wz[k], Wz[k]);
        w2[k] = pack2(Wn[k], Wn[k]);
    }
    const u64 bg0 = half ? 0ull : pack2(bih[j],      bih[j]);
    const u64 bg1 = half ? 0ull : pack2(bih[j + 16], bih[j + 16]);
    const u64 bg2 = half ? 0ull : pack2(bih[j + 32], bih[j + 32]);

    const ulonglong2* yrow =
        (const ulonglong2*)(g_y0p + ((size_t)t0 * (BB / 2) + p) * 32) + half * 8;
    uint4* go = g_gi + ((size_t)t0 * (BB / 2) + p) * 16 + j;

#pragma unroll 2
    for (int t = 0; t < 32; ++t) {
        u64 v[16];
#pragma unroll
        for (int q = 0; q < 8; ++q) {
            ulonglong2 u = yrow[q];
            v[2 * q] = u.x;
            v[2 * q + 1] = u.y;
        }
        u64 a0 = bg0, a1 = bg1, a2 = bg2;
#pragma unroll
        for (int k = 0; k < 16; ++k) {
            a0 = fma2(w0[k], v[k], a0);
            a1 = fma2(w1[k], v[k], a1);
            a2 = fma2(w2[k], v[k], a2);
        }
        a0 = add2(a0, __shfl_xor_sync(0xFFFFFFFFu, a0, 16));
        a1 = add2(a1, __shfl_xor_sync(0xFFFFFFFFu, a1, 16));
        a2 = add2(a2, __shfl_xor_sync(0xFFFFFFFFu, a2, 16));

        if (!half) {
            uint4 o;
            o.x = pair_to_h2(a0);
            o.y = pair_to_h2(a1);
            o.z = pair_to_h2(a2);
            o.w = 0u;
            *go = o;
        }

        yrow += (size_t)(BB / 2) * 16;     // next t (ulonglong2 units)
        go += (size_t)(BB / 2) * 16;       // next t (uint4 units)
    }
}

// ---------------------------------------------------------------------------
// Kernel 3: layer-1 forward recurrence (R7 shuffle structure). One LDG.128
// of fp16 gi per lane per step, converted to f32x2 at PREFETCH time (off the
// serial path); depth-4 ring.
// ---------------------------------------------------------------------------
__global__ void __launch_bounds__(128) gru_l1f(
    const float* __restrict__ Whh, const float* __restrict__ bhh,
    float* __restrict__ out)
{
    const int tid = threadIdx.x;
    const int j = tid & 15;
    const int P = blockIdx.x * 8 + (tid >> 4);
    const int b0 = 2 * P;

    u64 wr2[16], wz2[16], wn2[16];
#pragma unroll
    for (int k = 0; k < 16; ++k) {
        float a = Whh[(j)      * 16 + k];
        float b = Whh[(j + 16) * 16 + k];
        float c = Whh[(j + 32) * 16 + k];
        wr2[k] = pack2(a, a);
        wz2[k] = pack2(b, b);
        wn2[k] = pack2(c, c);
    }
    const u64 bhr2 = pack2(bhh[j], bhh[j]);
    const u64 bhz2 = pack2(bhh[j + 16], bhh[j + 16]);
    const u64 bhn2 = pack2(bhh[j + 32], bhh[j + 32]);
    const u64 zero2 = 0ull;

    const size_t ts = (size_t)(BB / 2) * 16;           // uint4 stride per t
    const uint4* gp = g_gi + (size_t)P * 16 + j;
    const uint4* pf = gp + 4 * ts;                     // prefetch cursor (t+4)

    u64 rr[4], rz[4], rn[4];
#pragma unroll
    for (int q = 0; q < 4; ++q) {
        uint4 gq = gp[(size_t)q * ts];
        rr[q] = h2_to_pair(gq.x);
        rz[q] = h2_to_pair(gq.y);
        rn[q] = h2_to_pair(gq.z);
    }

    u64 h2 = 0ull;
#pragma unroll 4
    for (int t = 0; t < TT; ++t) {
        const int sl = t & 3;
        u64 gr2 = rr[sl], gz2 = rz[sl], gn2 = rn[sl];
        if (t + 4 < TT) {
            uint4 gq = *pf;
            rr[sl] = h2_to_pair(gq.x);
            rz[sl] = h2_to_pair(gq.y);
            rn[sl] = h2_to_pair(gq.z);
        }
        pf += ts;

        u64 arA = bhr2, azA = bhz2, anA = bhn2;
        u64 arB = zero2, azB = zero2, anB = zero2;
#pragma unroll
        for (int k = 0; k < 8; ++k) {
            u64 hk = __shfl_sync(0xFFFFFFFFu, h2, k, 16);
            arA = fma2(wr2[k], hk, arA);
            azA = fma2(wz2[k], hk, azA);
            anA = fma2(wn2[k], hk, anA);
        }
#pragma unroll
        for (int k = 8; k < 16; ++k) {
            u64 hk = __shfl_sync(0xFFFFFFFFu, h2, k, 16);
            arB = fma2(wr2[k], hk, arB);
            azB = fma2(wz2[k], hk, azB);
            anB = fma2(wn2[k], hk, anB);
        }
        u64 pr = add2(gr2, add2(arA, arB));
        u64 pz = add2(gz2, add2(azA, azB));
        u64 an = add2(anA, anB);

        float prx, pry, pzx, pzy;
        unpack2(pr, prx, pry);
        unpack2(pz, pzx, pzy);
        float r0 = sigmoid_fast(prx), r1 = sigmoid_fast(pry);
        float z0 = sigmoid_fast(pzx), z1 = sigmoid_fast(pzy);

        u64 pn = fma2(pack2(r0, r1), an, gn2);
        float pnx, pny;
        unpack2(pn, pnx, pny);
        float n0 = tanh_fast(pnx), n1 = tanh_fast(pny);

        float h0, h1;
        unpack2(h2, h0, h1);
        h0 = n0 + z0 * (h0 - n0);
        h1 = n1 + z1 * (h1 - n1);
        h2 = pack2(h0, h1);
    }

    float h0, h1;
    unpack2(h2, h0, h1);
    out[b0 * 32 + j] = h0;
    out[(b0 + 1) * 32 + j] = h1;
}

// ---------------------------------------------------------------------------
// Kernel 4: layer-1 backward at position T-1 == one GRU step from h=0 on
// y0[T-1]. 17us measured — unchanged (reads pair-interleaved y0p).
// ---------------------------------------------------------------------------
__global__ void __launch_bounds__(128) gru_l1b(
    const float* __restrict__ Wih,
    const float* __restrict__ bih, const float* __restrict__ bhh,
    float* __restrict__ out)
{
    const int tid = threadIdx.x;
    const int j = tid & 15;
    const int e = tid >> 4;
    const int b = blockIdx.x * 8 + e;
    const int p = b >> 1;
    const int sel = b & 1;

    float wi0[32], wi1[32], wi2[32];
#pragma unroll
    for (int k = 0; k < 32; ++k) {
        wi0[k] = Wih[(j)      * 32 + k];
        wi1[k] = Wih[(j + 16) * 32 + k];
        wi2[k] = Wih[(j + 32) * 32 + k];
    }
    const float bir = bih[j], biz = bih[j + 16], bin_ = bih[j + 32];
    const float bhr = bhh[j], bhz = bhh[j + 16], bhn = bhh[j + 32];

    const ulonglong2* yrow =
        (const ulonglong2*)(g_y0p + ((size_t)(TT - 1) * (BB / 2) + p) * 32);
    ulonglong2 u2 = yrow[j];
    float ax, bx, ay, by;
    unpack2(u2.x, ax, bx);
    unpack2(u2.y, ay, by);
    float2 my;
    my.x = sel ? bx : ax;
    my.y = sel ? by : ay;

    float ir = bir, iz = biz, in_ = bin_;
#pragma unroll
    for (int k = 0; k < 16; ++k) {
        float vx = __shfl_sync(0xFFFFFFFFu, my.x, k, 16);
        float vy = __shfl_sync(0xFFFFFFFFu, my.y, k, 16);
        ir  = fmaf(wi0[2 * k], vx, ir);  ir  = fmaf(wi0[2 * k + 1], vy, ir);
        iz  = fmaf(wi1[2 * k], vx, iz);  iz  = fmaf(wi1[2 * k + 1], vy, iz);
        in_ = fmaf(wi2[2 * k], vx, in_); in_ = fmaf(wi2[2 * k + 1], vy, in_);
    }
    float r = sigmoid_fast(ir + bhr);
    float z = sigmoid_fast(iz + bhz);
    float n = tanh_fast(fmaf(r, bhn, in_));
    out[b * 32 + 16 + j] = (1.0f - z) * n;   // h0 = 0
}

// ---------------------------------------------------------------------------
// Launch. Inputs: x, then (Wih, Whh, bih, bhh) for l0_f, l0_b, l1_f, l1_b.
// Order: l0, l1b, proj, l1f (last launch = ncu capture slot = l1f).
// ---------------------------------------------------------------------------
extern "C" void kernel_launch(void* const* d_in, const int* in_sizes, int n_in,
                              void* d_out, int out_size) {
    const float* x = (const float*)d_in[0];

    dim3 g1(BB / 16, 2);
    gru_l0<<<g1, 64>>>(x,
        (const float*)d_in[1],  (const float*)d_in[2],
        (const float*)d_in[3],  (const float*)d_in[4],
        (const float*)d_in[5],  (const float*)d_in[6],
        (const float*)d_in[7],  (const float*)d_in[8]);

    gru_l1b<<<BB / 8, 128>>>(
        (const float*)d_in[13],
        (const float*)d_in[15], (const float*)d_in[16],
        (float*)d_out);

    dim3 g2(BB / 8, TT / 32);
    l1_proj<<<g2, 128>>>(
        (const float*)d_in[9],  (const float*)d_in[11]);

    gru_l1f<<<BB / 16, 128>>>(
        (const float*)d_in[10], (const float*)d_in[12],
        (float*)d_out);
}